// round 9
// baseline (speedup 1.0000x reference)
#include <cuda_runtime.h>
#include <cuda_bf16.h>
#include <cstdint>

// ---------------------------------------------------------------------------
// CustomFlashAttention — round 5
//   Projections: mma.sync.m16n8k16 bf16 hi/lo-split GEMM (baseline PTX: the
//     harness compiles for compute_103, so tcgen05/.cta_group ('a'-features)
//     are unavailable). fp32 register accumulators -> rel_err ~1e-5.
//   Attention: fp32 FFMA2 flash attention with natural padded SMEM layouts
//     (fixes the 32-way transposed-store bank conflicts seen in R3 ncu).
// ---------------------------------------------------------------------------

#define SEQ     2048
#define DMODEL  2048
#define NHEADS  16
#define HDIM    128

__device__ float g_Q[SEQ * DMODEL];
__device__ float g_K[SEQ * DMODEL];
__device__ float g_V[SEQ * DMODEL];
__device__ float g_O[SEQ * DMODEL];
__device__ __nv_bfloat16 g_Ahi[SEQ * DMODEL];
__device__ __nv_bfloat16 g_Alo[SEQ * DMODEL];
__device__ __nv_bfloat16 g_Whi[DMODEL * DMODEL];
__device__ __nv_bfloat16 g_Wlo[DMODEL * DMODEL];

typedef unsigned long long u64;

// ---------------- fp32x2 helpers (attention) ----------------
__device__ __forceinline__ u64 dup2(float x) {
    u64 r; asm("mov.b64 %0, {%1, %1};" : "=l"(r) : "f"(x)); return r;
}
__device__ __forceinline__ void ffma2(u64& d, u64 a, u64 b) {
    asm("fma.rn.f32x2 %0, %1, %2, %0;" : "+l"(d) : "l"(a), "l"(b));
}
__device__ __forceinline__ u64 fmul2(u64 a, u64 b) {
    u64 r; asm("mul.rn.f32x2 %0, %1, %2;" : "=l"(r) : "l"(a), "l"(b)); return r;
}
union F4 { float4 f; u64 p[2]; };

// ---------------- baseline-PTX tensor helpers ----------------
__device__ __forceinline__ uint32_t smem_u32(const void* p) {
    uint32_t a;
    asm("{ .reg .u64 t; cvta.to.shared.u64 t, %1; cvt.u32.u64 %0, t; }"
        : "=r"(a) : "l"(p));
    return a;
}
__device__ __forceinline__ void cp16(uint32_t dst, const void* src) {
    asm volatile("cp.async.cg.shared.global [%0], [%1], 16;"
                 :: "r"(dst), "l"(src));
}
#define CP_COMMIT() asm volatile("cp.async.commit_group;" ::: "memory")
#define CP_WAIT(n)  asm volatile("cp.async.wait_group %0;" :: "n"(n) : "memory")

__device__ __forceinline__ void ldsm4(uint32_t* r, uint32_t addr) {
    asm volatile("ldmatrix.sync.aligned.m8n8.x4.shared.b16 {%0,%1,%2,%3}, [%4];"
                 : "=r"(r[0]), "=r"(r[1]), "=r"(r[2]), "=r"(r[3]) : "r"(addr));
}
__device__ __forceinline__ void mma_bf16(float* c, const uint32_t* a,
                                         const uint32_t* b) {
    asm volatile(
        "mma.sync.aligned.m16n8k16.row.col.f32.bf16.bf16.f32 "
        "{%0,%1,%2,%3}, {%4,%5,%6,%7}, {%8,%9}, {%0,%1,%2,%3};"
        : "+f"(c[0]), "+f"(c[1]), "+f"(c[2]), "+f"(c[3])
        : "r"(a[0]), "r"(a[1]), "r"(a[2]), "r"(a[3]), "r"(b[0]), "r"(b[1]));
}
__device__ __forceinline__ uint32_t swz(uint32_t bo) {
    return bo ^ ((bo >> 3) & 0x70);
}

// ---------------------------------------------------------------------------
// fp32 -> bf16 hi/lo split (4 elems / thread)
// ---------------------------------------------------------------------------
__global__ void __launch_bounds__(256) conv_split_kernel(
    const float* __restrict__ src, __nv_bfloat16* __restrict__ hi,
    __nv_bfloat16* __restrict__ lo)
{
    int i = (blockIdx.x * 256 + threadIdx.x) * 4;
    float4 v = *(const float4*)(src + i);
    __nv_bfloat16 h0 = __float2bfloat16(v.x);
    __nv_bfloat16 h1 = __float2bfloat16(v.y);
    __nv_bfloat16 h2 = __float2bfloat16(v.z);
    __nv_bfloat16 h3 = __float2bfloat16(v.w);
    __nv_bfloat16 l0 = __float2bfloat16(v.x - __bfloat162float(h0));
    __nv_bfloat16 l1 = __float2bfloat16(v.y - __bfloat162float(h1));
    __nv_bfloat16 l2 = __float2bfloat16(v.z - __bfloat162float(h2));
    __nv_bfloat16 l3 = __float2bfloat16(v.w - __bfloat162float(h3));
    *(__nv_bfloat162*)(hi + i)     = __nv_bfloat162(h0, h1);
    *(__nv_bfloat162*)(hi + i + 2) = __nv_bfloat162(h2, h3);
    *(__nv_bfloat162*)(lo + i)     = __nv_bfloat162(l0, l1);
    *(__nv_bfloat162*)(lo + i + 2) = __nv_bfloat162(l2, l3);
}

// ---------------------------------------------------------------------------
// mma.sync bf16-split GEMM: C[M,N] = A @ B^T (A[M,K], B[N,K] row-major).
// C = Ahi*Bhi + Ahi*Blo + Alo*Bhi, fp32 accumulators.
// 128x128 tile, K-chunk 64 (128B swizzled rows), 256 threads (8 warps 2x4),
// cp.async double buffering.
// ---------------------------------------------------------------------------
#define BKC 64
#define TILE_BYTES 16384                   // 128 rows x 128B
#define STAGE_BYTES (4 * TILE_BYTES)       // Ahi, Alo, Bhi, Blo
#define AB_HI 0
#define AB_LO TILE_BYTES
#define BB_HI (2 * TILE_BYTES)
#define BB_LO (3 * TILE_BYTES)
#define GEMM_SMEM (2 * STAGE_BYTES)        // 128 KB

__device__ __forceinline__ void gemm_issue_chunk(
    uint32_t sb, int stage, int t,
    const __nv_bfloat16* Ahi, const __nv_bfloat16* Alo,
    const __nv_bfloat16* Bhi, const __nv_bfloat16* Blo,
    int m0, int n0, int k0)
{
    const uint32_t base = sb + stage * STAGE_BYTES;
    const int K = DMODEL;
#pragma unroll
    for (int i = 0; i < 4; i++) {
        int p = t + i * 256;               // 0..1023
        int row = p >> 3, c8 = p & 7;      // row 0..127, 16B-chunk 0..7
        uint32_t sw = swz((uint32_t)(row * 128 + c8 * 16));
        size_t ga = (size_t)(m0 + row) * K + k0 + c8 * 8;
        size_t gb = (size_t)(n0 + row) * K + k0 + c8 * 8;
        cp16(base + AB_HI + sw, Ahi + ga);
        cp16(base + AB_LO + sw, Alo + ga);
        cp16(base + BB_HI + sw, Bhi + gb);
        cp16(base + BB_LO + sw, Blo + gb);
    }
    CP_COMMIT();
}

__global__ void __launch_bounds__(256, 1) gemm_bf16split_kernel(
    const __nv_bfloat16* __restrict__ Ahi, const __nv_bfloat16* __restrict__ Alo,
    const __nv_bfloat16* __restrict__ Bhi, const __nv_bfloat16* __restrict__ Blo,
    float* __restrict__ C)
{
    extern __shared__ char smem[];
    const uint32_t sb = smem_u32(smem);
    const int t    = threadIdx.x;
    const int wid  = t >> 5;
    const int lane = t & 31;
    const int m0 = blockIdx.y * 128;
    const int n0 = blockIdx.x * 128;

    const int wm0 = (wid >> 2) * 64;       // warp m-offset within tile
    const int wn0 = (wid & 3) * 32;        // warp n-offset within tile

    float acc[4][4][4];                    // [mi][ni][frag]
#pragma unroll
    for (int mi = 0; mi < 4; mi++)
#pragma unroll
        for (int ni = 0; ni < 4; ni++)
#pragma unroll
            for (int q = 0; q < 4; q++) acc[mi][ni][q] = 0.0f;

    // ldmatrix lane addressing (swizzled, matching cp.async store layout)
    const int a_row_l = lane & 15;
    const int a_kb_l  = ((lane >> 4) & 1) * 16;
    const int b_row_l = (lane & 7) + ((lane >> 4) & 1) * 8;
    const int b_kb_l  = ((lane >> 3) & 1) * 16;

    const int nchunk = DMODEL / BKC;       // 32

    gemm_issue_chunk(sb, 0, t, Ahi, Alo, Bhi, Blo, m0, n0, 0);

    for (int kt = 0; kt < nchunk; kt++) {
        if (kt + 1 < nchunk) {
            gemm_issue_chunk(sb, (kt + 1) & 1, t, Ahi, Alo, Bhi, Blo,
                             m0, n0, (kt + 1) * BKC);
            CP_WAIT(1);
        } else {
            CP_WAIT(0);
        }
        __syncthreads();

        const uint32_t st = sb + (kt & 1) * STAGE_BYTES;
#pragma unroll
        for (int kk = 0; kk < 4; kk++) {
            uint32_t ah[4][4], al[4][4];
#pragma unroll
            for (int mi = 0; mi < 4; mi++) {
                uint32_t bo = (uint32_t)((wm0 + mi * 16 + a_row_l) * 128 +
                                         kk * 32 + a_kb_l);
                uint32_t sw = swz(bo);
                ldsm4(ah[mi], st + AB_HI + sw);
                ldsm4(al[mi], st + AB_LO + sw);
            }
            uint32_t bh[4][2], bl[4][2];
#pragma unroll
            for (int nj = 0; nj < 2; nj++) {
                uint32_t bo = (uint32_t)((wn0 + nj * 16 + b_row_l) * 128 +
                                         kk * 32 + b_kb_l);
                uint32_t sw = swz(bo);
                uint32_t r4[4];
                ldsm4(r4, st + BB_HI + sw);
                bh[nj * 2][0] = r4[0]; bh[nj * 2][1] = r4[1];
                bh[nj * 2 + 1][0] = r4[2]; bh[nj * 2 + 1][1] = r4[3];
                ldsm4(r4, st + BB_LO + sw);
                bl[nj * 2][0] = r4[0]; bl[nj * 2][1] = r4[1];
                bl[nj * 2 + 1][0] = r4[2]; bl[nj * 2 + 1][1] = r4[3];
            }
#pragma unroll
            for (int mi = 0; mi < 4; mi++)
#pragma unroll
                for (int ni = 0; ni < 4; ni++) {
                    mma_bf16(acc[mi][ni], ah[mi], bh[ni]);
                    mma_bf16(acc[mi][ni], ah[mi], bl[ni]);
                    mma_bf16(acc[mi][ni], al[mi], bh[ni]);
                }
        }
        __syncthreads();
    }

    // epilogue: fragment (c0,c1) -> row r, cols c..c+1; (c2,c3) -> row r+8
#pragma unroll
    for (int mi = 0; mi < 4; mi++) {
        int r = m0 + wm0 + mi * 16 + (lane >> 2);
#pragma unroll
        for (int ni = 0; ni < 4; ni++) {
            int c = n0 + wn0 + ni * 8 + (lane & 3) * 2;
            float* p0 = C + (size_t)r * DMODEL + c;
            float* p1 = C + (size_t)(r + 8) * DMODEL + c;
            p0[0] = acc[mi][ni][0]; p0[1] = acc[mi][ni][1];
            p1[0] = acc[mi][ni][2]; p1[1] = acc[mi][ni][3];
        }
    }
}

// ---------------------------------------------------------------------------
// Flash attention (fp32 / FFMA2), natural padded layouts (conflict-free).
// One block per (64-query tile, head). 512 threads.
// ---------------------------------------------------------------------------
#define BQ   64
#define BKT  64
#define AT   512
#define QLD  132
#define KLD  132
#define VLD  128
#define SLD  66

#define OFF_Q 0
#define OFF_K (OFF_Q + BQ * QLD)
#define OFF_V (OFF_K + BKT * KLD)
#define OFF_S (OFF_V + BKT * VLD)
#define OFF_M (OFF_S + BQ * SLD)
#define OFF_L (OFF_M + BQ)
#define OFF_F (OFF_L + BQ)
#define ATTN_SMEM ((OFF_F + BQ) * 4)

__global__ void __launch_bounds__(AT) attn_kernel(
    const float* __restrict__ Q, const float* __restrict__ K,
    const float* __restrict__ V, float* __restrict__ O)
{
    extern __shared__ float sm[];
    float* Qs    = sm + OFF_Q;
    float* Ks    = sm + OFF_K;
    float* Vs    = sm + OFF_V;
    float* Ss    = sm + OFF_S;
    float* row_m = sm + OFF_M;
    float* row_l = sm + OFF_L;
    float* row_f = sm + OFF_F;

    const int t    = threadIdx.x;
    const int tx   = t & 15;
    const int ty   = t >> 4;          // 0..31
    const int q0   = blockIdx.x * BQ;
    const int hoff = blockIdx.y * HDIM;

#pragma unroll
    for (int i = 0; i < 4; i++) {
        int p = t + i * AT;            // 0..2047
        int row = p >> 5, c4 = p & 31;
        float4 v = *(const float4*)(Q + (size_t)(q0 + row) * DMODEL + hoff + c4 * 4);
        *(float4*)&Qs[row * QLD + c4 * 4] = v;
    }
    if (t < BQ) { row_m[t] = -1e30f; row_l[t] = 0.0f; }

    const int r0  = ty * 2;            // 2 query rows per thread
    const int j0  = tx * 4;            // phase-2: 4 key cols
    const int dd0 = tx * 8;            // phase-3: 8 output dims

    u64 o2[2][4];
#pragma unroll
    for (int i = 0; i < 2; i++)
#pragma unroll
        for (int c = 0; c < 4; c++) o2[i][c] = 0ULL;

    const float scale = 0.0883883476483184406f;  // 1/sqrt(128)

    for (int kt = 0; kt < SEQ / BKT; kt++) {
        const int kbase = kt * BKT;
        __syncthreads();

#pragma unroll
        for (int i = 0; i < 4; i++) {
            int p = t + i * AT;
            int row = p >> 5, c4 = p & 31;
            float4 kv = *(const float4*)(K + (size_t)(kbase + row) * DMODEL + hoff + c4 * 4);
            *(float4*)&Ks[row * KLD + c4 * 4] = kv;
            float4 vv = *(const float4*)(V + (size_t)(kbase + row) * DMODEL + hoff + c4 * 4);
            *(float4*)&Vs[row * VLD + c4 * 4] = vv;
        }
        __syncthreads();

        // phase 2: S[2][4] = Q K^T  (f32x2 pair accumulation along d)
        {
            u64 acc[16];
#pragma unroll
            for (int i = 0; i < 16; i++) acc[i] = 0ULL;
#pragma unroll 2
            for (int d = 0; d < HDIM; d += 4) {
                F4 qa0, qa1, kb0, kb1, kb2, kb3;
                qa0.f = *(const float4*)&Qs[(r0 + 0) * QLD + d];
                qa1.f = *(const float4*)&Qs[(r0 + 1) * QLD + d];
                kb0.f = *(const float4*)&Ks[(j0 + 0) * KLD + d];
                kb1.f = *(const float4*)&Ks[(j0 + 1) * KLD + d];
                kb2.f = *(const float4*)&Ks[(j0 + 2) * KLD + d];
                kb3.f = *(const float4*)&Ks[(j0 + 3) * KLD + d];
#pragma unroll
                for (int p = 0; p < 2; p++) {
                    ffma2(acc[0 + p],  qa0.p[p], kb0.p[p]);
                    ffma2(acc[2 + p],  qa0.p[p], kb1.p[p]);
                    ffma2(acc[4 + p],  qa0.p[p], kb2.p[p]);
                    ffma2(acc[6 + p],  qa0.p[p], kb3.p[p]);
                    ffma2(acc[8 + p],  qa1.p[p], kb0.p[p]);
                    ffma2(acc[10 + p], qa1.p[p], kb1.p[p]);
                    ffma2(acc[12 + p], qa1.p[p], kb2.p[p]);
                    ffma2(acc[14 + p], qa1.p[p], kb3.p[p]);
                }
            }
#pragma unroll
            for (int i = 0; i < 2; i++)
#pragma unroll
                for (int jj = 0; jj < 4; jj++) {
                    F4 a;
                    a.p[0] = acc[i * 8 + jj * 2];
                    a.p[1] = acc[i * 8 + jj * 2 + 1];
                    float s = (a.f.x + a.f.y + a.f.z + a.f.w) * scale;
                    Ss[(r0 + i) * SLD + j0 + jj] = s;
                }
        }
        __syncthreads();

        // softmax update: 8 threads per query row
        {
            const int row = t >> 3;
            const int qd  = t & 7;
            float* srow = &Ss[row * SLD + qd * 8];
            float mloc = -1e30f;
#pragma unroll
            for (int j = 0; j < 8; j++) mloc = fmaxf(mloc, srow[j]);
            mloc = fmaxf(mloc, __shfl_xor_sync(0xffffffffu, mloc, 1));
            mloc = fmaxf(mloc, __shfl_xor_sync(0xffffffffu, mloc, 2));
            mloc = fmaxf(mloc, __shfl_xor_sync(0xffffffffu, mloc, 4));
            const float mold = row_m[row];
            const float mnew = fmaxf(mold, mloc);
            float lloc = 0.0f;
#pragma unroll
            for (int j = 0; j < 8; j++) {
                float p = __expf(srow[j] - mnew);
                srow[j] = p;
                lloc += p;
            }
            lloc += __shfl_xor_sync(0xffffffffu, lloc, 1);
            lloc += __shfl_xor_sync(0xffffffffu, lloc, 2);
            lloc += __shfl_xor_sync(0xffffffffu, lloc, 4);
            if (qd == 0) {
                float f = __expf(mold - mnew);
                row_f[row] = f;
                row_l[row] = row_l[row] * f + lloc;
                row_m[row] = mnew;
            }
        }
        __syncthreads();

        // phase 3: O = O*f + P V
        {
            u64 f0 = dup2(row_f[r0]);
            u64 f1 = dup2(row_f[r0 + 1]);
#pragma unroll
            for (int c = 0; c < 4; c++) {
                o2[0][c] = fmul2(o2[0][c], f0);
                o2[1][c] = fmul2(o2[1][c], f1);
            }
#pragma unroll 4
            for (int j = 0; j < BKT; j++) {
                F4 v0, v1;
                v0.f = *(const float4*)&Vs[j * VLD + dd0];
                v1.f = *(const float4*)&Vs[j * VLD + dd0 + 4];
                u64 p0 = dup2(Ss[(r0)     * SLD + j]);
                u64 p1 = dup2(Ss[(r0 + 1) * SLD + j]);
                ffma2(o2[0][0], p0, v0.p[0]); ffma2(o2[0][1], p0, v0.p[1]);
                ffma2(o2[0][2], p0, v1.p[0]); ffma2(o2[0][3], p0, v1.p[1]);
                ffma2(o2[1][0], p1, v0.p[0]); ffma2(o2[1][1], p1, v0.p[1]);
                ffma2(o2[1][2], p1, v1.p[0]); ffma2(o2[1][3], p1, v1.p[1]);
            }
        }
    }

    // normalize and store
    {
#pragma unroll
        for (int i = 0; i < 2; i++) {
            u64 inv = dup2(1.0f / row_l[r0 + i]);
            float* orow = O + (size_t)(q0 + r0 + i) * DMODEL + hoff + dd0;
            *(u64*)(orow + 0) = fmul2(o2[i][0], inv);
            *(u64*)(orow + 2) = fmul2(o2[i][1], inv);
            *(u64*)(orow + 4) = fmul2(o2[i][2], inv);
            *(u64*)(orow + 6) = fmul2(o2[i][3], inv);
        }
    }
}

// ---------------------------------------------------------------------------
// Launch
// ---------------------------------------------------------------------------
extern "C" void kernel_launch(void* const* d_in, const int* in_sizes, int n_in,
                              void* d_out, int out_size)
{
    (void)in_sizes; (void)n_in; (void)out_size;

    const float* x  = (const float*)d_in[0];
    const float* wq = (const float*)d_in[1];
    const float* wk = (const float*)d_in[2];
    const float* wv = (const float*)d_in[3];
    const float* wo = (const float*)d_in[4];
    float* out = (float*)d_out;

    float *pQ, *pK, *pV, *pO;
    __nv_bfloat16 *pAhi, *pAlo, *pWhi, *pWlo;
    cudaGetSymbolAddress((void**)&pQ, g_Q);
    cudaGetSymbolAddress((void**)&pK, g_K);
    cudaGetSymbolAddress((void**)&pV, g_V);
    cudaGetSymbolAddress((void**)&pO, g_O);
    cudaGetSymbolAddress((void**)&pAhi, g_Ahi);
    cudaGetSymbolAddress((void**)&pAlo, g_Alo);
    cudaGetSymbolAddress((void**)&pWhi, g_Whi);
    cudaGetSymbolAddress((void**)&pWlo, g_Wlo);

    cudaFuncSetAttribute(gemm_bf16split_kernel,
                         cudaFuncAttributeMaxDynamicSharedMemorySize, GEMM_SMEM);
    cudaFuncSetAttribute(attn_kernel,
                         cudaFuncAttributeMaxDynamicSharedMemorySize, ATTN_SMEM);

    const int convBlocks = (SEQ * DMODEL) / (256 * 4);
    dim3 gg(DMODEL / 128, SEQ / 128);

    conv_split_kernel<<<convBlocks, 256>>>(x, pAhi, pAlo);

    conv_split_kernel<<<convBlocks, 256>>>(wq, pWhi, pWlo);
    gemm_bf16split_kernel<<<gg, 256, GEMM_SMEM>>>(pAhi, pAlo, pWhi, pWlo, pQ);

    conv_split_kernel<<<convBlocks, 256>>>(wk, pWhi, pWlo);
    gemm_bf16split_kernel<<<gg, 256, GEMM_SMEM>>>(pAhi, pAlo, pWhi, pWlo, pK);

    conv_split_kernel<<<convBlocks, 256>>>(wv, pWhi, pWlo);
    gemm_bf16split_kernel<<<gg, 256, GEMM_SMEM>>>(pAhi, pAlo, pWhi, pWlo, pV);

    attn_kernel<<<dim3(SEQ / BQ, NHEADS), AT, ATTN_SMEM>>>(pQ, pK, pV, pO);

    conv_split_kernel<<<convBlocks, 256>>>(pO, pAhi, pAlo);
    conv_split_kernel<<<convBlocks, 256>>>(wo, pWhi, pWlo);
    gemm_bf16split_kernel<<<gg, 256, GEMM_SMEM>>>(pAhi, pAlo, pWhi, pWlo, out);
}

// round 10
// speedup vs baseline: 1.2429x; 1.2429x over previous
#include <cuda_runtime.h>
#include <cstdint>

// ---------------------------------------------------------------------------
// CustomFlashAttention — round 10
//   All-fp32 FFMA2 pipeline. tcgen05 is uncompilable (harness targets
//   compute_103, no 'a' features) and mma.sync measured at ~66 TF/s on this
//   chip (same as the FFMA2 pipe) making the 3-MMA hi/lo split strictly
//   worse. So: R3's proven FFMA2 gemm_tn (projections) + R9's conflict-free
//   padded-layout flash attention.
// ---------------------------------------------------------------------------

#define SEQ     2048
#define DMODEL  2048
#define NHEADS  16
#define HDIM    128

__device__ float g_Q[SEQ * DMODEL];
__device__ float g_K[SEQ * DMODEL];
__device__ float g_V[SEQ * DMODEL];
__device__ float g_O[SEQ * DMODEL];

typedef unsigned long long u64;

__device__ __forceinline__ u64 dup2(float x) {
    u64 r; asm("mov.b64 %0, {%1, %1};" : "=l"(r) : "f"(x)); return r;
}
__device__ __forceinline__ void ffma2(u64& d, u64 a, u64 b) {
    asm("fma.rn.f32x2 %0, %1, %2, %0;" : "+l"(d) : "l"(a), "l"(b));
}
__device__ __forceinline__ u64 fmul2(u64 a, u64 b) {
    u64 r; asm("mul.rn.f32x2 %0, %1, %2;" : "=l"(r) : "l"(a), "l"(b)); return r;
}
union F4 { float4 f; u64 p[2]; };

// ---------------------------------------------------------------------------
// GEMM: C[M,N] = A[M,K] @ B[N,K]^T  (row-major). 128x128 tile, BK=16,
// 256 threads, 8x8 micro-tile as 8 rows x 4 f32x2 col-pairs. (R3-proven.)
// ---------------------------------------------------------------------------
#define BM 128
#define BN 128
#define BK 16
#define GT 256

__global__ void __launch_bounds__(GT, 2) gemm_tn_kernel(
    const float* __restrict__ A, const float* __restrict__ B,
    float* __restrict__ C, int M, int N, int K)
{
    __shared__ float As[BK][BM];   // transposed: As[k][m]
    __shared__ float Bs[BK][BN];   // transposed: Bs[k][n]

    const int t  = threadIdx.x;
    const int tx = t & 15;         // N direction (8 cols = 4 pairs)
    const int ty = t >> 4;         // M direction (8 rows)
    const int m0 = blockIdx.y * BM;
    const int n0 = blockIdx.x * BN;

    u64 acc[8][4];
#pragma unroll
    for (int r = 0; r < 8; r++)
#pragma unroll
        for (int c = 0; c < 4; c++) acc[r][c] = 0ULL;

    const int nkt = K / BK;

    // prologue: stage 0 straight into SMEM
    {
#pragma unroll
        for (int i = 0; i < 2; i++) {
            int p = t + i * 256;           // 0..511 -> 512 float4 per matrix
            int row = p >> 2;              // 0..127
            int kq  = p & 3;               // which float4 along K
            float4 va = *(const float4*)(A + (size_t)(m0 + row) * K + kq * 4);
            float4 vb = *(const float4*)(B + (size_t)(n0 + row) * K + kq * 4);
            As[kq * 4 + 0][row] = va.x; As[kq * 4 + 1][row] = va.y;
            As[kq * 4 + 2][row] = va.z; As[kq * 4 + 3][row] = va.w;
            Bs[kq * 4 + 0][row] = vb.x; Bs[kq * 4 + 1][row] = vb.y;
            Bs[kq * 4 + 2][row] = vb.z; Bs[kq * 4 + 3][row] = vb.w;
        }
    }
    __syncthreads();

    float4 ra[2], rb[2];
    for (int kt = 1; kt <= nkt; kt++) {
        // prefetch next stage into registers
        if (kt < nkt) {
            int k0 = kt * BK;
#pragma unroll
            for (int i = 0; i < 2; i++) {
                int p = t + i * 256;
                int row = p >> 2, kq = p & 3;
                ra[i] = *(const float4*)(A + (size_t)(m0 + row) * K + k0 + kq * 4);
                rb[i] = *(const float4*)(B + (size_t)(n0 + row) * K + k0 + kq * 4);
            }
        }
        // compute current stage
#pragma unroll
        for (int kk = 0; kk < BK; kk++) {
            float4 a0 = *(const float4*)&As[kk][ty * 8];
            float4 a1 = *(const float4*)&As[kk][ty * 8 + 4];
            const u64* bp = (const u64*)&Bs[kk][tx * 8];
            u64 b0 = bp[0], b1 = bp[1], b2 = bp[2], b3 = bp[3];
            u64 ad[8];
            ad[0] = dup2(a0.x); ad[1] = dup2(a0.y);
            ad[2] = dup2(a0.z); ad[3] = dup2(a0.w);
            ad[4] = dup2(a1.x); ad[5] = dup2(a1.y);
            ad[6] = dup2(a1.z); ad[7] = dup2(a1.w);
#pragma unroll
            for (int r = 0; r < 8; r++) {
                ffma2(acc[r][0], ad[r], b0);
                ffma2(acc[r][1], ad[r], b1);
                ffma2(acc[r][2], ad[r], b2);
                ffma2(acc[r][3], ad[r], b3);
            }
        }
        __syncthreads();
        if (kt < nkt) {
#pragma unroll
            for (int i = 0; i < 2; i++) {
                int p = t + i * 256;
                int row = p >> 2, kq = p & 3;
                As[kq * 4 + 0][row] = ra[i].x; As[kq * 4 + 1][row] = ra[i].y;
                As[kq * 4 + 2][row] = ra[i].z; As[kq * 4 + 3][row] = ra[i].w;
                Bs[kq * 4 + 0][row] = rb[i].x; Bs[kq * 4 + 1][row] = rb[i].y;
                Bs[kq * 4 + 2][row] = rb[i].z; Bs[kq * 4 + 3][row] = rb[i].w;
            }
            __syncthreads();
        }
    }

    // epilogue: STG.64 per f32x2 pair
#pragma unroll
    for (int r = 0; r < 8; r++) {
        float* crow = C + (size_t)(m0 + ty * 8 + r) * N + n0 + tx * 8;
#pragma unroll
        for (int c = 0; c < 4; c++) {
            *(u64*)(crow + c * 2) = acc[r][c];
        }
    }
}

// ---------------------------------------------------------------------------
// Flash attention (fp32 / FFMA2), natural padded layouts (conflict-free).
// One block per (64-query tile, head). 512 threads. (R9-proven.)
// ---------------------------------------------------------------------------
#define BQ   64
#define BKT  64
#define AT   512
#define QLD  132
#define KLD  132
#define VLD  128
#define SLD  66

#define OFF_Q 0
#define OFF_K (OFF_Q + BQ * QLD)
#define OFF_V (OFF_K + BKT * KLD)
#define OFF_S (OFF_V + BKT * VLD)
#define OFF_M (OFF_S + BQ * SLD)
#define OFF_L (OFF_M + BQ)
#define OFF_F (OFF_L + BQ)
#define ATTN_SMEM ((OFF_F + BQ) * 4)

__global__ void __launch_bounds__(AT) attn_kernel(
    const float* __restrict__ Q, const float* __restrict__ K,
    const float* __restrict__ V, float* __restrict__ O)
{
    extern __shared__ float sm[];
    float* Qs    = sm + OFF_Q;
    float* Ks    = sm + OFF_K;
    float* Vs    = sm + OFF_V;
    float* Ss    = sm + OFF_S;
    float* row_m = sm + OFF_M;
    float* row_l = sm + OFF_L;
    float* row_f = sm + OFF_F;

    const int t    = threadIdx.x;
    const int tx   = t & 15;
    const int ty   = t >> 4;          // 0..31
    const int q0   = blockIdx.x * BQ;
    const int hoff = blockIdx.y * HDIM;

#pragma unroll
    for (int i = 0; i < 4; i++) {
        int p = t + i * AT;            // 0..2047
        int row = p >> 5, c4 = p & 31;
        float4 v = *(const float4*)(Q + (size_t)(q0 + row) * DMODEL + hoff + c4 * 4);
        *(float4*)&Qs[row * QLD + c4 * 4] = v;
    }
    if (t < BQ) { row_m[t] = -1e30f; row_l[t] = 0.0f; }

    const int r0  = ty * 2;            // 2 query rows per thread
    const int j0  = tx * 4;            // phase-2: 4 key cols
    const int dd0 = tx * 8;            // phase-3: 8 output dims

    u64 o2[2][4];
#pragma unroll
    for (int i = 0; i < 2; i++)
#pragma unroll
        for (int c = 0; c < 4; c++) o2[i][c] = 0ULL;

    const float scale = 0.0883883476483184406f;  // 1/sqrt(128)

    for (int kt = 0; kt < SEQ / BKT; kt++) {
        const int kbase = kt * BKT;
        __syncthreads();

#pragma unroll
        for (int i = 0; i < 4; i++) {
            int p = t + i * AT;
            int row = p >> 5, c4 = p & 31;
            float4 kv = *(const float4*)(K + (size_t)(kbase + row) * DMODEL + hoff + c4 * 4);
            *(float4*)&Ks[row * KLD + c4 * 4] = kv;
            float4 vv = *(const float4*)(V + (size_t)(kbase + row) * DMODEL + hoff + c4 * 4);
            *(float4*)&Vs[row * VLD + c4 * 4] = vv;
        }
        __syncthreads();

        // phase 2: S[2][4] = Q K^T  (f32x2 pair accumulation along d)
        {
            u64 acc[16];
#pragma unroll
            for (int i = 0; i < 16; i++) acc[i] = 0ULL;
#pragma unroll 2
            for (int d = 0; d < HDIM; d += 4) {
                F4 qa0, qa1, kb0, kb1, kb2, kb3;
                qa0.f = *(const float4*)&Qs[(r0 + 0) * QLD + d];
                qa1.f = *(const float4*)&Qs[(r0 + 1) * QLD + d];
                kb0.f = *(const float4*)&Ks[(j0 + 0) * KLD + d];
                kb1.f = *(const float4*)&Ks[(j0 + 1) * KLD + d];
                kb2.f = *(const float4*)&Ks[(j0 + 2) * KLD + d];
                kb3.f = *(const float4*)&Ks[(j0 + 3) * KLD + d];
#pragma unroll
                for (int p = 0; p < 2; p++) {
                    ffma2(acc[0 + p],  qa0.p[p], kb0.p[p]);
                    ffma2(acc[2 + p],  qa0.p[p], kb1.p[p]);
                    ffma2(acc[4 + p],  qa0.p[p], kb2.p[p]);
                    ffma2(acc[6 + p],  qa0.p[p], kb3.p[p]);
                    ffma2(acc[8 + p],  qa1.p[p], kb0.p[p]);
                    ffma2(acc[10 + p], qa1.p[p], kb1.p[p]);
                    ffma2(acc[12 + p], qa1.p[p], kb2.p[p]);
                    ffma2(acc[14 + p], qa1.p[p], kb3.p[p]);
                }
            }
#pragma unroll
            for (int i = 0; i < 2; i++)
#pragma unroll
                for (int jj = 0; jj < 4; jj++) {
                    F4 a;
                    a.p[0] = acc[i * 8 + jj * 2];
                    a.p[1] = acc[i * 8 + jj * 2 + 1];
                    float s = (a.f.x + a.f.y + a.f.z + a.f.w) * scale;
                    Ss[(r0 + i) * SLD + j0 + jj] = s;
                }
        }
        __syncthreads();

        // softmax update: 8 threads per query row
        {
            const int row = t >> 3;
            const int qd  = t & 7;
            float* srow = &Ss[row * SLD + qd * 8];
            float mloc = -1e30f;
#pragma unroll
            for (int j = 0; j < 8; j++) mloc = fmaxf(mloc, srow[j]);
            mloc = fmaxf(mloc, __shfl_xor_sync(0xffffffffu, mloc, 1));
            mloc = fmaxf(mloc, __shfl_xor_sync(0xffffffffu, mloc, 2));
            mloc = fmaxf(mloc, __shfl_xor_sync(0xffffffffu, mloc, 4));
            const float mold = row_m[row];
            const float mnew = fmaxf(mold, mloc);
            float lloc = 0.0f;
#pragma unroll
            for (int j = 0; j < 8; j++) {
                float p = __expf(srow[j] - mnew);
                srow[j] = p;
                lloc += p;
            }
            lloc += __shfl_xor_sync(0xffffffffu, lloc, 1);
            lloc += __shfl_xor_sync(0xffffffffu, lloc, 2);
            lloc += __shfl_xor_sync(0xffffffffu, lloc, 4);
            if (qd == 0) {
                float f = __expf(mold - mnew);
                row_f[row] = f;
                row_l[row] = row_l[row] * f + lloc;
                row_m[row] = mnew;
            }
        }
        __syncthreads();

        // phase 3: O = O*f + P V
        {
            u64 f0 = dup2(row_f[r0]);
            u64 f1 = dup2(row_f[r0 + 1]);
#pragma unroll
            for (int c = 0; c < 4; c++) {
                o2[0][c] = fmul2(o2[0][c], f0);
                o2[1][c] = fmul2(o2[1][c], f1);
            }
#pragma unroll 4
            for (int j = 0; j < BKT; j++) {
                F4 v0, v1;
                v0.f = *(const float4*)&Vs[j * VLD + dd0];
                v1.f = *(const float4*)&Vs[j * VLD + dd0 + 4];
                u64 p0 = dup2(Ss[(r0)     * SLD + j]);
                u64 p1 = dup2(Ss[(r0 + 1) * SLD + j]);
                ffma2(o2[0][0], p0, v0.p[0]); ffma2(o2[0][1], p0, v0.p[1]);
                ffma2(o2[0][2], p0, v1.p[0]); ffma2(o2[0][3], p0, v1.p[1]);
                ffma2(o2[1][0], p1, v0.p[0]); ffma2(o2[1][1], p1, v0.p[1]);
                ffma2(o2[1][2], p1, v1.p[0]); ffma2(o2[1][3], p1, v1.p[1]);
            }
        }
    }

    // normalize and store
    {
#pragma unroll
        for (int i = 0; i < 2; i++) {
            u64 inv = dup2(1.0f / row_l[r0 + i]);
            float* orow = O + (size_t)(q0 + r0 + i) * DMODEL + hoff + dd0;
            *(u64*)(orow + 0) = fmul2(o2[i][0], inv);
            *(u64*)(orow + 2) = fmul2(o2[i][1], inv);
            *(u64*)(orow + 4) = fmul2(o2[i][2], inv);
            *(u64*)(orow + 6) = fmul2(o2[i][3], inv);
        }
    }
}

// ---------------------------------------------------------------------------
// Launch
// ---------------------------------------------------------------------------
extern "C" void kernel_launch(void* const* d_in, const int* in_sizes, int n_in,
                              void* d_out, int out_size)
{
    (void)in_sizes; (void)n_in; (void)out_size;

    const float* x  = (const float*)d_in[0];
    const float* wq = (const float*)d_in[1];
    const float* wk = (const float*)d_in[2];
    const float* wv = (const float*)d_in[3];
    const float* wo = (const float*)d_in[4];
    float* out = (float*)d_out;

    float *pQ, *pK, *pV, *pO;
    cudaGetSymbolAddress((void**)&pQ, g_Q);
    cudaGetSymbolAddress((void**)&pK, g_K);
    cudaGetSymbolAddress((void**)&pV, g_V);
    cudaGetSymbolAddress((void**)&pO, g_O);

    cudaFuncSetAttribute(attn_kernel,
                         cudaFuncAttributeMaxDynamicSharedMemorySize, ATTN_SMEM);

    dim3 gg(DMODEL / BN, SEQ / BM);
    gemm_tn_kernel<<<gg, GT>>>(x, wq, pQ, SEQ, DMODEL, DMODEL);
    gemm_tn_kernel<<<gg, GT>>>(x, wk, pK, SEQ, DMODEL, DMODEL);
    gemm_tn_kernel<<<gg, GT>>>(x, wv, pV, SEQ, DMODEL, DMODEL);

    attn_kernel<<<dim3(SEQ / BQ, NHEADS), AT, ATTN_SMEM>>>(pQ, pK, pV, pO);

    gemm_tn_kernel<<<gg, GT>>>(pO, wo, out, SEQ, DMODEL, DMODEL);
}

// round 13
// speedup vs baseline: 2.3435x; 1.8855x over previous
#include <cuda_runtime.h>
#include <cstdint>

// ---------------------------------------------------------------------------
// CustomFlashAttention — round 11
//   GEMMs: R3-proven FFMA2 gemm_tn (~95% of fp32x2 pipe ceiling).
//   Attention: rebuilt with bank-exact SMEM layouts:
//     - Q/K tiles XOR-swizzled (group ^ (row&7)) -> conflict-free stores AND
//       conflict-free K loads (keys strided tx+16*jj so j&7 differs per lane)
//     - phase-3 V reads at 4*tx d-offsets (all 32 banks per phase)
//     - 8 rows x 4 keys per thread (Q broadcast reuse, fma:crossbar ~ 1:1)
// ---------------------------------------------------------------------------

#define SEQ     2048
#define DMODEL  2048
#define NHEADS  16
#define HDIM    128

__device__ float g_Q[SEQ * DMODEL];
__device__ float g_K[SEQ * DMODEL];
__device__ float g_V[SEQ * DMODEL];
__device__ float g_O[SEQ * DMODEL];

typedef unsigned long long u64;

__device__ __forceinline__ u64 dup2(float x) {
    u64 r; asm("mov.b64 %0, {%1, %1};" : "=l"(r) : "f"(x)); return r;
}
__device__ __forceinline__ void ffma2(u64& d, u64 a, u64 b) {
    asm("fma.rn.f32x2 %0, %1, %2, %0;" : "+l"(d) : "l"(a), "l"(b));
}
__device__ __forceinline__ u64 fmul2(u64 a, u64 b) {
    u64 r; asm("mul.rn.f32x2 %0, %1, %2;" : "=l"(r) : "l"(a), "l"(b)); return r;
}
union F4 { float4 f; u64 p[2]; float s[4]; };

// ---------------------------------------------------------------------------
// GEMM: C[M,N] = A[M,K] @ B[N,K]^T  (row-major). 128x128 tile, BK=16,
// 256 threads, 8x8 micro-tile as 8 rows x 4 f32x2 col-pairs. (R3-proven.)
// ---------------------------------------------------------------------------
#define BM 128
#define BN 128
#define BK 16
#define GT 256

__global__ void __launch_bounds__(GT, 2) gemm_tn_kernel(
    const float* __restrict__ A, const float* __restrict__ B,
    float* __restrict__ C, int M, int N, int K)
{
    __shared__ float As[BK][BM];
    __shared__ float Bs[BK][BN];

    const int t  = threadIdx.x;
    const int tx = t & 15;
    const int ty = t >> 4;
    const int m0 = blockIdx.y * BM;
    const int n0 = blockIdx.x * BN;

    u64 acc[8][4];
#pragma unroll
    for (int r = 0; r < 8; r++)
#pragma unroll
        for (int c = 0; c < 4; c++) acc[r][c] = 0ULL;

    const int nkt = K / BK;

    {
#pragma unroll
        for (int i = 0; i < 2; i++) {
            int p = t + i * 256;
            int row = p >> 2;
            int kq  = p & 3;
            float4 va = *(const float4*)(A + (size_t)(m0 + row) * K + kq * 4);
            float4 vb = *(const float4*)(B + (size_t)(n0 + row) * K + kq * 4);
            As[kq * 4 + 0][row] = va.x; As[kq * 4 + 1][row] = va.y;
            As[kq * 4 + 2][row] = va.z; As[kq * 4 + 3][row] = va.w;
            Bs[kq * 4 + 0][row] = vb.x; Bs[kq * 4 + 1][row] = vb.y;
            Bs[kq * 4 + 2][row] = vb.z; Bs[kq * 4 + 3][row] = vb.w;
        }
    }
    __syncthreads();

    float4 ra[2], rb[2];
    for (int kt = 1; kt <= nkt; kt++) {
        if (kt < nkt) {
            int k0 = kt * BK;
#pragma unroll
            for (int i = 0; i < 2; i++) {
                int p = t + i * 256;
                int row = p >> 2, kq = p & 3;
                ra[i] = *(const float4*)(A + (size_t)(m0 + row) * K + k0 + kq * 4);
                rb[i] = *(const float4*)(B + (size_t)(n0 + row) * K + k0 + kq * 4);
            }
        }
#pragma unroll
        for (int kk = 0; kk < BK; kk++) {
            float4 a0 = *(const float4*)&As[kk][ty * 8];
            float4 a1 = *(const float4*)&As[kk][ty * 8 + 4];
            const u64* bp = (const u64*)&Bs[kk][tx * 8];
            u64 b0 = bp[0], b1 = bp[1], b2 = bp[2], b3 = bp[3];
            u64 ad[8];
            ad[0] = dup2(a0.x); ad[1] = dup2(a0.y);
            ad[2] = dup2(a0.z); ad[3] = dup2(a0.w);
            ad[4] = dup2(a1.x); ad[5] = dup2(a1.y);
            ad[6] = dup2(a1.z); ad[7] = dup2(a1.w);
#pragma unroll
            for (int r = 0; r < 8; r++) {
                ffma2(acc[r][0], ad[r], b0);
                ffma2(acc[r][1], ad[r], b1);
                ffma2(acc[r][2], ad[r], b2);
                ffma2(acc[r][3], ad[r], b3);
            }
        }
        __syncthreads();
        if (kt < nkt) {
#pragma unroll
            for (int i = 0; i < 2; i++) {
                int p = t + i * 256;
                int row = p >> 2, kq = p & 3;
                As[kq * 4 + 0][row] = ra[i].x; As[kq * 4 + 1][row] = ra[i].y;
                As[kq * 4 + 2][row] = ra[i].z; As[kq * 4 + 3][row] = ra[i].w;
                Bs[kq * 4 + 0][row] = rb[i].x; Bs[kq * 4 + 1][row] = rb[i].y;
                Bs[kq * 4 + 2][row] = rb[i].z; Bs[kq * 4 + 3][row] = rb[i].w;
            }
            __syncthreads();
        }
    }

#pragma unroll
    for (int r = 0; r < 8; r++) {
        float* crow = C + (size_t)(m0 + ty * 8 + r) * N + n0 + tx * 8;
#pragma unroll
        for (int c = 0; c < 4; c++) {
            *(u64*)(crow + c * 2) = acc[r][c];
        }
    }
}

// ---------------------------------------------------------------------------
// Flash attention, bank-exact layouts. One block per (128-query tile, head),
// 256 threads, key tile 64.
//   Q/K swizzled: word(row,d) = row*128 + ((g ^ (row&7))<<2) + (d&3), g=d>>2
//   thread (tx=t&15, ty=t>>4): phase2 rows ty*8..+7, keys {tx+16*jj}
//   phase3 d-cols {4tx..4tx+3, 64+4tx..64+4tx+3}
// ---------------------------------------------------------------------------
#define BQ   128
#define BKT  64
#define AT   256
#define SLD  66

#define AOFF_Q 0
#define AOFF_K (AOFF_Q + BQ * 128)
#define AOFF_V (AOFF_K + BKT * 128)
#define AOFF_S (AOFF_V + BKT * 128)
#define AOFF_M (AOFF_S + BQ * SLD)
#define AOFF_L (AOFF_M + BQ)
#define AOFF_F (AOFF_L + BQ)
#define ATTN_SMEM ((AOFF_F + BQ) * 4)

__device__ __forceinline__ int qk_word(int row, int g) {
    return row * 128 + (((g ^ (row & 7)) & 31) << 2);
}

__global__ void __launch_bounds__(AT) attn_kernel(
    const float* __restrict__ Q, const float* __restrict__ K,
    const float* __restrict__ V, float* __restrict__ O)
{
    extern __shared__ float sm[];
    float* Qs    = sm + AOFF_Q;
    float* Ks    = sm + AOFF_K;
    float* Vs    = sm + AOFF_V;
    float* Ss    = sm + AOFF_S;
    float* row_m = sm + AOFF_M;
    float* row_l = sm + AOFF_L;
    float* row_f = sm + AOFF_F;

    const int t    = threadIdx.x;
    const int tx   = t & 15;
    const int ty   = t >> 4;           // 0..15
    const int q0   = blockIdx.x * BQ;
    const int hoff = blockIdx.y * HDIM;

    // stage Q tile (swizzled), once
#pragma unroll
    for (int i = 0; i < 16; i++) {
        int p = t + i * AT;            // 0..4095
        int row = p >> 5, g = p & 31;
        float4 v = *(const float4*)(Q + (size_t)(q0 + row) * DMODEL + hoff + g * 4);
        *(float4*)&Qs[qk_word(row, g)] = v;
    }
    if (t < BQ) { row_m[t] = -1e30f; row_l[t] = 0.0f; }

    const int r0 = ty * 8;             // 8 query rows per thread

    u64 oa[8][2], ob[8][2];            // O accum: d in {4tx..}, {64+4tx..}
#pragma unroll
    for (int i = 0; i < 8; i++) {
        oa[i][0] = oa[i][1] = 0ULL;
        ob[i][0] = ob[i][1] = 0ULL;
    }

    const float scale = 0.0883883476483184406f;  // 1/sqrt(128)

    for (int kt = 0; kt < SEQ / BKT; kt++) {
        const int kbase = kt * BKT;
        __syncthreads();               // prev phase-3 done with Ks/Vs/Ss

        // stage K (swizzled) + V (natural)
#pragma unroll
        for (int i = 0; i < 8; i++) {
            int p = t + i * AT;        // 0..2047
            int row = p >> 5, g = p & 31;
            float4 kv = *(const float4*)(K + (size_t)(kbase + row) * DMODEL + hoff + g * 4);
            *(float4*)&Ks[qk_word(row, g)] = kv;
            float4 vv = *(const float4*)(V + (size_t)(kbase + row) * DMODEL + hoff + g * 4);
            *(float4*)&Vs[row * 128 + g * 4] = vv;
        }
        __syncthreads();

        // phase 2: S = Q K^T, 8 rows x 4 keys (keys tx+16*jj), conflict-free
        {
            u64 sacc[8][4];
#pragma unroll
            for (int i = 0; i < 8; i++)
#pragma unroll
                for (int jj = 0; jj < 4; jj++) sacc[i][jj] = 0ULL;

#pragma unroll 4
            for (int g = 0; g < 32; g++) {
                F4 kb[4];
#pragma unroll
                for (int jj = 0; jj < 4; jj++) {
                    int j = tx + 16 * jj;
                    kb[jj].f = *(const float4*)&Ks[j * 128 + (((g ^ (tx & 7)) & 31) << 2)];
                }
#pragma unroll
                for (int i = 0; i < 8; i++) {
                    F4 qa;
                    qa.f = *(const float4*)&Qs[(r0 + i) * 128 + (((g ^ (i & 7)) & 31) << 2)];
#pragma unroll
                    for (int jj = 0; jj < 4; jj++) {
                        ffma2(sacc[i][jj], qa.p[0], kb[jj].p[0]);
                        ffma2(sacc[i][jj], qa.p[1], kb[jj].p[1]);
                    }
                }
            }
#pragma unroll
            for (int i = 0; i < 8; i++)
#pragma unroll
                for (int jj = 0; jj < 4; jj++) {
                    F4 a; a.p[0] = sacc[i][jj];
                    float s = (a.s[0] + a.s[1]) * scale;
                    Ss[(r0 + i) * SLD + tx + 16 * jj] = s;
                }
        }
        __syncthreads();

        // softmax: 2 threads per row, 32 scores each
        {
            const int row = t >> 1;
            const int qd  = t & 1;
            float* srow = &Ss[row * SLD + qd * 32];
            float mloc = -1e30f;
#pragma unroll
            for (int j = 0; j < 32; j++) mloc = fmaxf(mloc, srow[j]);
            mloc = fmaxf(mloc, __shfl_xor_sync(0xffffffffu, mloc, 1));
            const float mold = row_m[row];
            const float mnew = fmaxf(mold, mloc);
            float lloc = 0.0f;
#pragma unroll
            for (int j = 0; j < 32; j++) {
                float p = __expf(srow[j] - mnew);
                srow[j] = p;
                lloc += p;
            }
            lloc += __shfl_xor_sync(0xffffffffu, lloc, 1);
            if (qd == 0) {
                float f = __expf(mold - mnew);
                row_f[row] = f;
                row_l[row] = row_l[row] * f + lloc;
                row_m[row] = mnew;
            }
        }
        __syncthreads();

        // phase 3: O = O*f + P V   (V float4 at 4tx / 64+4tx: conflict-free)
        {
#pragma unroll
            for (int i = 0; i < 8; i++) {
                u64 fd = dup2(row_f[r0 + i]);
                oa[i][0] = fmul2(oa[i][0], fd); oa[i][1] = fmul2(oa[i][1], fd);
                ob[i][0] = fmul2(ob[i][0], fd); ob[i][1] = fmul2(ob[i][1], fd);
            }
#pragma unroll 4
            for (int j = 0; j < BKT; j++) {
                F4 va, vb;
                va.f = *(const float4*)&Vs[j * 128 + 4 * tx];
                vb.f = *(const float4*)&Vs[j * 128 + 64 + 4 * tx];
#pragma unroll
                for (int i = 0; i < 8; i++) {
                    u64 pd = dup2(Ss[(r0 + i) * SLD + j]);
                    ffma2(oa[i][0], pd, va.p[0]); ffma2(oa[i][1], pd, va.p[1]);
                    ffma2(ob[i][0], pd, vb.p[0]); ffma2(ob[i][1], pd, vb.p[1]);
                }
            }
        }
    }

    // normalize and store (STG.128 per half)
#pragma unroll
    for (int i = 0; i < 8; i++) {
        u64 inv = dup2(1.0f / row_l[r0 + i]);
        float* orow = O + (size_t)(q0 + r0 + i) * DMODEL + hoff;
        F4 wa, wb;
        wa.p[0] = fmul2(oa[i][0], inv); wa.p[1] = fmul2(oa[i][1], inv);
        wb.p[0] = fmul2(ob[i][0], inv); wb.p[1] = fmul2(ob[i][1], inv);
        *(float4*)(orow + 4 * tx)      = wa.f;
        *(float4*)(orow + 64 + 4 * tx) = wb.f;
    }
}

// ---------------------------------------------------------------------------
// Launch
// ---------------------------------------------------------------------------
extern "C" void kernel_launch(void* const* d_in, const int* in_sizes, int n_in,
                              void* d_out, int out_size)
{
    (void)in_sizes; (void)n_in; (void)out_size;

    const float* x  = (const float*)d_in[0];
    const float* wq = (const float*)d_in[1];
    const float* wk = (const float*)d_in[2];
    const float* wv = (const float*)d_in[3];
    const float* wo = (const float*)d_in[4];
    float* out = (float*)d_out;

    float *pQ, *pK, *pV, *pO;
    cudaGetSymbolAddress((void**)&pQ, g_Q);
    cudaGetSymbolAddress((void**)&pK, g_K);
    cudaGetSymbolAddress((void**)&pV, g_V);
    cudaGetSymbolAddress((void**)&pO, g_O);

    cudaFuncSetAttribute(attn_kernel,
                         cudaFuncAttributeMaxDynamicSharedMemorySize, ATTN_SMEM);

    dim3 gg(DMODEL / BN, SEQ / BM);
    gemm_tn_kernel<<<gg, GT>>>(x, wq, pQ, SEQ, DMODEL, DMODEL);
    gemm_tn_kernel<<<gg, GT>>>(x, wk, pK, SEQ, DMODEL, DMODEL);
    gemm_tn_kernel<<<gg, GT>>>(x, wv, pV, SEQ, DMODEL, DMODEL);

    attn_kernel<<<dim3(SEQ / BQ, NHEADS), AT, ATTN_SMEM>>>(pQ, pK, pV, pO);

    gemm_tn_kernel<<<gg, GT>>>(pO, wo, out, SEQ, DMODEL, DMODEL);
}

// round 14
// speedup vs baseline: 2.3795x; 1.0154x over previous
#include <cuda_runtime.h>
#include <cstdint>

// ---------------------------------------------------------------------------
// CustomFlashAttention — round 14
//   GEMMs: FFMA2 gemm_tn with smem double-buffering (1 barrier per K-chunk,
//     LDG hidden under compute).  R13 measured 40 TF/s; target ~50.
//   Attention: R13 bank-exact swizzled kernel widened to 512 threads
//     (16 warps/SM vs 8) with 4 rows x 4 keys per thread; same smem.
// ---------------------------------------------------------------------------

#define SEQ     2048
#define DMODEL  2048
#define NHEADS  16
#define HDIM    128

__device__ float g_Q[SEQ * DMODEL];
__device__ float g_K[SEQ * DMODEL];
__device__ float g_V[SEQ * DMODEL];
__device__ float g_O[SEQ * DMODEL];

typedef unsigned long long u64;

__device__ __forceinline__ u64 dup2(float x) {
    u64 r; asm("mov.b64 %0, {%1, %1};" : "=l"(r) : "f"(x)); return r;
}
__device__ __forceinline__ void ffma2(u64& d, u64 a, u64 b) {
    asm("fma.rn.f32x2 %0, %1, %2, %0;" : "+l"(d) : "l"(a), "l"(b));
}
__device__ __forceinline__ u64 fmul2(u64 a, u64 b) {
    u64 r; asm("mul.rn.f32x2 %0, %1, %2;" : "=l"(r) : "l"(a), "l"(b)); return r;
}
union F4 { float4 f; u64 p[2]; float s[4]; };

// ---------------------------------------------------------------------------
// GEMM: C[M,N] = A[M,K] @ B[N,K]^T (row-major). 128x128 tile, BK=16,
// 256 threads, 8x8 micro-tile, double-buffered smem (1 barrier per chunk).
// ---------------------------------------------------------------------------
#define BM 128
#define BN 128
#define BK 16
#define GT 256

__global__ void __launch_bounds__(GT, 2) gemm_tn_kernel(
    const float* __restrict__ A, const float* __restrict__ B,
    float* __restrict__ C, int M, int N, int K)
{
    __shared__ float As[2][BK][BM];
    __shared__ float Bs[2][BK][BN];

    const int t  = threadIdx.x;
    const int tx = t & 15;
    const int ty = t >> 4;
    const int m0 = blockIdx.y * BM;
    const int n0 = blockIdx.x * BN;

    u64 acc[8][4];
#pragma unroll
    for (int r = 0; r < 8; r++)
#pragma unroll
        for (int c = 0; c < 4; c++) acc[r][c] = 0ULL;

    const int nkt = K / BK;
    const int row = t >> 2;            // 0..127  (staging role)
    const int kq  = t & 3;

    float4 ra[2], rb[2];

    // prologue: chunk 0 -> buf0 directly; chunk 1 -> regs
#pragma unroll
    for (int i = 0; i < 2; i++) {
        int rr = row, qq = kq;         // p = t + i*256 decomposition
        if (i == 1) { rr = row + 64; } // t+256: row += 64, kq same
        float4 va = *(const float4*)(A + (size_t)(m0 + rr) * K + qq * 4);
        float4 vb = *(const float4*)(B + (size_t)(n0 + rr) * K + qq * 4);
        As[0][qq * 4 + 0][rr] = va.x; As[0][qq * 4 + 1][rr] = va.y;
        As[0][qq * 4 + 2][rr] = va.z; As[0][qq * 4 + 3][rr] = va.w;
        Bs[0][qq * 4 + 0][rr] = vb.x; Bs[0][qq * 4 + 1][rr] = vb.y;
        Bs[0][qq * 4 + 2][rr] = vb.z; Bs[0][qq * 4 + 3][rr] = vb.w;
    }
    if (nkt > 1) {
#pragma unroll
        for (int i = 0; i < 2; i++) {
            int rr = row + i * 64;
            ra[i] = *(const float4*)(A + (size_t)(m0 + rr) * K + BK + kq * 4);
            rb[i] = *(const float4*)(B + (size_t)(n0 + rr) * K + BK + kq * 4);
        }
    }
    __syncthreads();

    for (int kt = 0; kt < nkt; kt++) {
        const int cur = kt & 1;
        // stage chunk kt+1 (from regs) into the other buffer
        if (kt + 1 < nkt) {
            const int nxt = cur ^ 1;
#pragma unroll
            for (int i = 0; i < 2; i++) {
                int rr = row + i * 64;
                As[nxt][kq * 4 + 0][rr] = ra[i].x; As[nxt][kq * 4 + 1][rr] = ra[i].y;
                As[nxt][kq * 4 + 2][rr] = ra[i].z; As[nxt][kq * 4 + 3][rr] = ra[i].w;
                Bs[nxt][kq * 4 + 0][rr] = rb[i].x; Bs[nxt][kq * 4 + 1][rr] = rb[i].y;
                Bs[nxt][kq * 4 + 2][rr] = rb[i].z; Bs[nxt][kq * 4 + 3][rr] = rb[i].w;
            }
        }
        // prefetch chunk kt+2 into regs (latency hidden under compute)
        if (kt + 2 < nkt) {
            int k0 = (kt + 2) * BK;
#pragma unroll
            for (int i = 0; i < 2; i++) {
                int rr = row + i * 64;
                ra[i] = *(const float4*)(A + (size_t)(m0 + rr) * K + k0 + kq * 4);
                rb[i] = *(const float4*)(B + (size_t)(n0 + rr) * K + k0 + kq * 4);
            }
        }
        // compute current chunk
#pragma unroll
        for (int kk = 0; kk < BK; kk++) {
            float4 a0 = *(const float4*)&As[cur][kk][ty * 8];
            float4 a1 = *(const float4*)&As[cur][kk][ty * 8 + 4];
            const u64* bp = (const u64*)&Bs[cur][kk][tx * 8];
            u64 b0 = bp[0], b1 = bp[1], b2 = bp[2], b3 = bp[3];
            u64 ad[8];
            ad[0] = dup2(a0.x); ad[1] = dup2(a0.y);
            ad[2] = dup2(a0.z); ad[3] = dup2(a0.w);
            ad[4] = dup2(a1.x); ad[5] = dup2(a1.y);
            ad[6] = dup2(a1.z); ad[7] = dup2(a1.w);
#pragma unroll
            for (int r = 0; r < 8; r++) {
                ffma2(acc[r][0], ad[r], b0);
                ffma2(acc[r][1], ad[r], b1);
                ffma2(acc[r][2], ad[r], b2);
                ffma2(acc[r][3], ad[r], b3);
            }
        }
        __syncthreads();
    }

#pragma unroll
    for (int r = 0; r < 8; r++) {
        float* crow = C + (size_t)(m0 + ty * 8 + r) * N + n0 + tx * 8;
#pragma unroll
        for (int c = 0; c < 4; c++) {
            *(u64*)(crow + c * 2) = acc[r][c];
        }
    }
}

// ---------------------------------------------------------------------------
// Flash attention, bank-exact swizzled layouts (R13), widened to 512 threads.
// One block per (128-query tile, head); 4 rows x 4 keys per thread.
// ---------------------------------------------------------------------------
#define BQ   128
#define BKT  64
#define AT   512
#define SLD  66

#define AOFF_Q 0
#define AOFF_K (AOFF_Q + BQ * 128)
#define AOFF_V (AOFF_K + BKT * 128)
#define AOFF_S (AOFF_V + BKT * 128)
#define AOFF_M (AOFF_S + BQ * SLD)
#define AOFF_L (AOFF_M + BQ)
#define AOFF_F (AOFF_L + BQ)
#define ATTN_SMEM ((AOFF_F + BQ) * 4)

__device__ __forceinline__ int qk_word(int row, int g) {
    return row * 128 + (((g ^ (row & 7)) & 31) << 2);
}

__global__ void __launch_bounds__(AT, 1) attn_kernel(
    const float* __restrict__ Q, const float* __restrict__ K,
    const float* __restrict__ V, float* __restrict__ O)
{
    extern __shared__ float sm[];
    float* Qs    = sm + AOFF_Q;
    float* Ks    = sm + AOFF_K;
    float* Vs    = sm + AOFF_V;
    float* Ss    = sm + AOFF_S;
    float* row_m = sm + AOFF_M;
    float* row_l = sm + AOFF_L;
    float* row_f = sm + AOFF_F;

    const int t    = threadIdx.x;
    const int tx   = t & 15;
    const int ty   = t >> 4;           // 0..31
    const int q0   = blockIdx.x * BQ;
    const int hoff = blockIdx.y * HDIM;

    // stage Q tile (swizzled), once
#pragma unroll
    for (int i = 0; i < 8; i++) {
        int p = t + i * AT;            // 0..4095
        int row = p >> 5, g = p & 31;
        float4 v = *(const float4*)(Q + (size_t)(q0 + row) * DMODEL + hoff + g * 4);
        *(float4*)&Qs[qk_word(row, g)] = v;
    }
    if (t < BQ) { row_m[t] = -1e30f; row_l[t] = 0.0f; }

    const int r0 = ty * 4;             // 4 query rows per thread

    u64 oa[4][2], ob[4][2];            // O accum: d in {4tx..}, {64+4tx..}
#pragma unroll
    for (int i = 0; i < 4; i++) {
        oa[i][0] = oa[i][1] = 0ULL;
        ob[i][0] = ob[i][1] = 0ULL;
    }

    const float scale = 0.0883883476483184406f;  // 1/sqrt(128)

    for (int kt = 0; kt < SEQ / BKT; kt++) {
        const int kbase = kt * BKT;
        __syncthreads();               // prev phase-3 done with Ks/Vs/Ss

        // stage K (swizzled) + V (natural)
#pragma unroll
        for (int i = 0; i < 4; i++) {
            int p = t + i * AT;        // 0..2047
            int row = p >> 5, g = p & 31;
            float4 kv = *(const float4*)(K + (size_t)(kbase + row) * DMODEL + hoff + g * 4);
            *(float4*)&Ks[qk_word(row, g)] = kv;
            float4 vv = *(const float4*)(V + (size_t)(kbase + row) * DMODEL + hoff + g * 4);
            *(float4*)&Vs[row * 128 + g * 4] = vv;
        }
        __syncthreads();

        // phase 2: S = Q K^T, 4 rows x 4 keys (keys tx+16*jj)
        {
            u64 sacc[4][4];
#pragma unroll
            for (int i = 0; i < 4; i++)
#pragma unroll
                for (int jj = 0; jj < 4; jj++) sacc[i][jj] = 0ULL;

#pragma unroll 4
            for (int g = 0; g < 32; g++) {
                F4 kb[4];
#pragma unroll
                for (int jj = 0; jj < 4; jj++) {
                    int j = tx + 16 * jj;
                    kb[jj].f = *(const float4*)&Ks[j * 128 + (((g ^ (tx & 7)) & 31) << 2)];
                }
#pragma unroll
                for (int i = 0; i < 4; i++) {
                    F4 qa;
                    qa.f = *(const float4*)&Qs[(r0 + i) * 128 + (((g ^ ((r0 + i) & 7)) & 31) << 2)];
#pragma unroll
                    for (int jj = 0; jj < 4; jj++) {
                        ffma2(sacc[i][jj], qa.p[0], kb[jj].p[0]);
                        ffma2(sacc[i][jj], qa.p[1], kb[jj].p[1]);
                    }
                }
            }
#pragma unroll
            for (int i = 0; i < 4; i++)
#pragma unroll
                for (int jj = 0; jj < 4; jj++) {
                    F4 a; a.p[0] = sacc[i][jj];
                    float s = (a.s[0] + a.s[1]) * scale;
                    Ss[(r0 + i) * SLD + tx + 16 * jj] = s;
                }
        }
        __syncthreads();

        // softmax: 4 threads per row, 16 scores each
        {
            const int row = t >> 2;
            const int qd  = t & 3;
            float* srow = &Ss[row * SLD + qd * 16];
            float mloc = -1e30f;
#pragma unroll
            for (int j = 0; j < 16; j++) mloc = fmaxf(mloc, srow[j]);
            mloc = fmaxf(mloc, __shfl_xor_sync(0xffffffffu, mloc, 1));
            mloc = fmaxf(mloc, __shfl_xor_sync(0xffffffffu, mloc, 2));
            const float mold = row_m[row];
            const float mnew = fmaxf(mold, mloc);
            float lloc = 0.0f;
#pragma unroll
            for (int j = 0; j < 16; j++) {
                float p = __expf(srow[j] - mnew);
                srow[j] = p;
                lloc += p;
            }
            lloc += __shfl_xor_sync(0xffffffffu, lloc, 1);
            lloc += __shfl_xor_sync(0xffffffffu, lloc, 2);
            if (qd == 0) {
                float f = __expf(mold - mnew);
                row_f[row] = f;
                row_l[row] = row_l[row] * f + lloc;
                row_m[row] = mnew;
            }
        }
        __syncthreads();

        // phase 3: O = O*f + P V   (V float4 at 4tx / 64+4tx)
        {
#pragma unroll
            for (int i = 0; i < 4; i++) {
                u64 fd = dup2(row_f[r0 + i]);
                oa[i][0] = fmul2(oa[i][0], fd); oa[i][1] = fmul2(oa[i][1], fd);
                ob[i][0] = fmul2(ob[i][0], fd); ob[i][1] = fmul2(ob[i][1], fd);
            }
#pragma unroll 4
            for (int j = 0; j < BKT; j++) {
                F4 va, vb;
                va.f = *(const float4*)&Vs[j * 128 + 4 * tx];
                vb.f = *(const float4*)&Vs[j * 128 + 64 + 4 * tx];
#pragma unroll
                for (int i = 0; i < 4; i++) {
                    u64 pd = dup2(Ss[(r0 + i) * SLD + j]);
                    ffma2(oa[i][0], pd, va.p[0]); ffma2(oa[i][1], pd, va.p[1]);
                    ffma2(ob[i][0], pd, vb.p[0]); ffma2(ob[i][1], pd, vb.p[1]);
                }
            }
        }
    }

    // normalize and store (STG.128 per half)
#pragma unroll
    for (int i = 0; i < 4; i++) {
        u64 inv = dup2(1.0f / row_l[r0 + i]);
        float* orow = O + (size_t)(q0 + r0 + i) * DMODEL + hoff;
        F4 wa, wb;
        wa.p[0] = fmul2(oa[i][0], inv); wa.p[1] = fmul2(oa[i][1], inv);
        wb.p[0] = fmul2(ob[i][0], inv); wb.p[1] = fmul2(ob[i][1], inv);
        *(float4*)(orow + 4 * tx)      = wa.f;
        *(float4*)(orow + 64 + 4 * tx) = wb.f;
    }
}

// ---------------------------------------------------------------------------
// Launch
// ---------------------------------------------------------------------------
extern "C" void kernel_launch(void* const* d_in, const int* in_sizes, int n_in,
                              void* d_out, int out_size)
{
    (void)in_sizes; (void)n_in; (void)out_size;

    const float* x  = (const float*)d_in[0];
    const float* wq = (const float*)d_in[1];
    const float* wk = (const float*)d_in[2];
    const float* wv = (const float*)d_in[3];
    const float* wo = (const float*)d_in[4];
    float* out = (float*)d_out;

    float *pQ, *pK, *pV, *pO;
    cudaGetSymbolAddress((void**)&pQ, g_Q);
    cudaGetSymbolAddress((void**)&pK, g_K);
    cudaGetSymbolAddress((void**)&pV, g_V);
    cudaGetSymbolAddress((void**)&pO, g_O);

    cudaFuncSetAttribute(attn_kernel,
                         cudaFuncAttributeMaxDynamicSharedMemorySize, ATTN_SMEM);

    dim3 gg(DMODEL / BN, SEQ / BM);
    gemm_tn_kernel<<<gg, GT>>>(x, wq, pQ, SEQ, DMODEL, DMODEL);
    gemm_tn_kernel<<<gg, GT>>>(x, wk, pK, SEQ, DMODEL, DMODEL);
    gemm_tn_kernel<<<gg, GT>>>(x, wv, pV, SEQ, DMODEL, DMODEL);

    attn_kernel<<<dim3(SEQ / BQ, NHEADS), AT, ATTN_SMEM>>>(pQ, pK, pV, pO);

    gemm_tn_kernel<<<gg, GT>>>(pO, wo, out, SEQ, DMODEL, DMODEL);
}